// round 4
// baseline (speedup 1.0000x reference)
#include <cuda_runtime.h>
#include <math.h>

#define BB 4
#define NN 256
#define DMID 128
#define DE 8
#define HH 8
#define DD 16
#define LL 2
#define NROWS (BB*NN)   // 1024
#define TI 16           // i-rows per attn block
#define JS 2            // j-splits

// ---------------- scratch (no allocations allowed) ----------------
__device__ float g_q[NROWS*DMID];
__device__ float g_k[NROWS*DMID];
__device__ float g_v[NROWS*DMID];
__device__ float g_res[NROWS*DMID];
__device__ float g_x[NROWS*DMID];
__device__ float g_means[NN];
// attention partials (per j-split)
__device__ float g_vp[JS*NROWS*DMID];
__device__ float g_ep[JS*NROWS*HH*DE];
__device__ float g_ws[JS*NROWS*HH];

// ---------------- projections: out = x @ W + b for q,k,v,res ----------------
__global__ void __launch_bounds__(128) proj_kernel(
    const float* __restrict__ x, int from_gx,
    const float* __restrict__ Wq, const float* __restrict__ bq,
    const float* __restrict__ Wk, const float* __restrict__ bk,
    const float* __restrict__ Wv, const float* __restrict__ bv,
    const float* __restrict__ Wr, const float* __restrict__ br)
{
    const float* W; const float* bias; float* out;
    switch (blockIdx.y) {
        case 0:  W = Wq; bias = bq; out = g_q;   break;
        case 1:  W = Wk; bias = bk; out = g_k;   break;
        case 2:  W = Wv; bias = bv; out = g_v;   break;
        default: W = Wr; bias = br; out = g_res; break;
    }
    __shared__ float xs[16][DMID];
    const int row0 = blockIdx.x * 16;
    const int t = threadIdx.x;           // 0..127 = output column
    const float* xsrc = from_gx ? g_x : x;
    #pragma unroll
    for (int r = 0; r < 16; r++)
        xs[r][t] = xsrc[(row0 + r) * DMID + t];
    __syncthreads();

    float acc[16];
    const float bv_ = bias[t];
    #pragma unroll
    for (int r = 0; r < 16; r++) acc[r] = bv_;

    for (int kk = 0; kk < DMID; kk++) {
        float w = W[kk * DMID + t];      // coalesced
        #pragma unroll
        for (int r = 0; r < 16; r++)
            acc[r] = fmaf(xs[r][kk], w, acc[r]);   // xs broadcast
    }
    #pragma unroll
    for (int r = 0; r < 16; r++)
        out[(row0 + r) * DMID + t] = acc[r];
}

// ---------------- means[i] = mean_j sim[b=0,h=0,i,j] (pre-mask) ----------------
__global__ void __launch_bounds__(256) means_kernel(
    const float* __restrict__ edges,
    const float* __restrict__ We, const float* __restrict__ be)
{
    const int i = blockIdx.x;
    const int j = threadIdx.x;  // 0..255
    __shared__ float q0[DD];
    __shared__ float Wes[DE][DD];
    __shared__ float bes[DD];
    __shared__ float red[8];

    if (j < DD) { q0[j] = g_q[i * DMID + j]; bes[j] = be[j]; }
    if (j < DE * DD) Wes[j / DD][j % DD] = We[(j / DD) * DMID + (j % DD)];
    __syncthreads();

    const float4* ep = (const float4*)(edges + ((size_t)i * NN + j) * DE);
    float4 e0 = ep[0], e1 = ep[1];
    float ed[DE] = {e0.x, e0.y, e0.z, e0.w, e1.x, e1.y, e1.z, e1.w};
    const float* krow = g_k + j * DMID;   // b=0 rows

    float acc = 0.f;
    #pragma unroll
    for (int d = 0; d < DD; d++) {
        float e = bes[d];
        #pragma unroll
        for (int c = 0; c < DE; c++) e = fmaf(ed[c], Wes[c][d], e);
        acc = fmaf(q0[d], krow[d] + e, acc);
    }
    #pragma unroll
    for (int off = 16; off; off >>= 1)
        acc += __shfl_xor_sync(0xffffffffu, acc, off);
    if ((j & 31) == 0) red[j >> 5] = acc;
    __syncthreads();
    if (j == 0) {
        float s = 0.f;
        #pragma unroll
        for (int w = 0; w < 8; w++) s += red[w];
        g_means[i] = s * (0.25f / (float)NN);   // scale=1/sqrt(16), /N
    }
}

// ---------------- attention: thread owns one (i,h); no shuffles ----------------
// sim_ij = qs·k_j + edges_ij·r + c0        (qs = 0.25*q)
// out contribution factored:  vacc += w*v_j[hd],  eacc += w*edges_ij,  ws += w
__global__ void __launch_bounds__(128) attn2_kernel(
    const float* __restrict__ edges, const float* __restrict__ adj,
    const float* __restrict__ We, const float* __restrict__ be)
{
    const int t  = threadIdx.x;
    const int h  = t & 7;
    const int il = t >> 3;                 // 0..15
    const int i  = blockIdx.x * TI + il;
    const int jh = blockIdx.y;             // 0..JS-1
    const int b  = blockIdx.z;
    const int row = b * NN + i;
    const int hd  = h * DD;

    // q segment (pre-scaled by softmax scale)
    float qs[DD];
    {
        const float4* q4 = (const float4*)(g_q + (size_t)row * DMID + hd);
        #pragma unroll
        for (int s4 = 0; s4 < 4; s4++) {
            float4 qv = q4[s4];
            qs[s4*4+0] = qv.x * 0.25f; qs[s4*4+1] = qv.y * 0.25f;
            qs[s4*4+2] = qv.z * 0.25f; qs[s4*4+3] = qv.w * 0.25f;
        }
    }
    // r[c] = We[c,:]·qs ;  c0 = be·qs
    float r[DE];
    #pragma unroll
    for (int c = 0; c < DE; c++) {
        float s = 0.f;
        #pragma unroll
        for (int d = 0; d < DD; d++)
            s = fmaf(We[c * DMID + hd + d], qs[d], s);
        r[c] = s;
    }
    float c0 = 0.f;
    #pragma unroll
    for (int d = 0; d < DD; d++) c0 = fmaf(be[hd + d], qs[d], c0);

    const float mi = g_means[i];
    const float* kb = g_k + (size_t)b * NN * DMID;
    const float* vb = g_v + (size_t)b * NN * DMID;
    const float* er = edges + (size_t)row * NN * DE;
    const float* ar = adj + ((size_t)b * NN + i) * NN;

    float vacc[DD];
    #pragma unroll
    for (int d = 0; d < DD; d++) vacc[d] = 0.f;
    float eacc[DE];
    #pragma unroll
    for (int c = 0; c < DE; c++) eacc[c] = 0.f;
    float ws = 0.f;

    const int j0 = jh * (NN / JS), j1 = j0 + (NN / JS);
    #pragma unroll 2
    for (int j = j0; j < j1; j++) {
        const float4* ep = (const float4*)(er + (size_t)j * DE);
        float4 e0 = ep[0], e1 = ep[1];

        float p = c0;
        p = fmaf(e0.x, r[0], p); p = fmaf(e0.y, r[1], p);
        p = fmaf(e0.z, r[2], p); p = fmaf(e0.w, r[3], p);
        p = fmaf(e1.x, r[4], p); p = fmaf(e1.y, r[5], p);
        p = fmaf(e1.z, r[6], p); p = fmaf(e1.w, r[7], p);

        const float4* k4 = (const float4*)(kb + (size_t)j * DMID + hd);
        float4 ka = k4[0], kbv = k4[1], kc = k4[2], kd = k4[3];
        p = fmaf(qs[0],  ka.x,  p); p = fmaf(qs[1],  ka.y,  p);
        p = fmaf(qs[2],  ka.z,  p); p = fmaf(qs[3],  ka.w,  p);
        p = fmaf(qs[4],  kbv.x, p); p = fmaf(qs[5],  kbv.y, p);
        p = fmaf(qs[6],  kbv.z, p); p = fmaf(qs[7],  kbv.w, p);
        p = fmaf(qs[8],  kc.x,  p); p = fmaf(qs[9],  kc.y,  p);
        p = fmaf(qs[10], kc.z,  p); p = fmaf(qs[11], kc.w,  p);
        p = fmaf(qs[12], kd.x,  p); p = fmaf(qs[13], kd.y,  p);
        p = fmaf(qs[14], kd.z,  p); p = fmaf(qs[15], kd.w,  p);

        const float w = __expf(p - mi) * ar[j];

        const float4* v4 = (const float4*)(vb + (size_t)j * DMID + hd);
        float4 va = v4[0], vbv = v4[1], vc = v4[2], vd = v4[3];
        vacc[0]  = fmaf(w, va.x,  vacc[0]);  vacc[1]  = fmaf(w, va.y,  vacc[1]);
        vacc[2]  = fmaf(w, va.z,  vacc[2]);  vacc[3]  = fmaf(w, va.w,  vacc[3]);
        vacc[4]  = fmaf(w, vbv.x, vacc[4]);  vacc[5]  = fmaf(w, vbv.y, vacc[5]);
        vacc[6]  = fmaf(w, vbv.z, vacc[6]);  vacc[7]  = fmaf(w, vbv.w, vacc[7]);
        vacc[8]  = fmaf(w, vc.x,  vacc[8]);  vacc[9]  = fmaf(w, vc.y,  vacc[9]);
        vacc[10] = fmaf(w, vc.z,  vacc[10]); vacc[11] = fmaf(w, vc.w,  vacc[11]);
        vacc[12] = fmaf(w, vd.x,  vacc[12]); vacc[13] = fmaf(w, vd.y,  vacc[13]);
        vacc[14] = fmaf(w, vd.z,  vacc[14]); vacc[15] = fmaf(w, vd.w,  vacc[15]);

        eacc[0] = fmaf(w, e0.x, eacc[0]); eacc[1] = fmaf(w, e0.y, eacc[1]);
        eacc[2] = fmaf(w, e0.z, eacc[2]); eacc[3] = fmaf(w, e0.w, eacc[3]);
        eacc[4] = fmaf(w, e1.x, eacc[4]); eacc[5] = fmaf(w, e1.y, eacc[5]);
        eacc[6] = fmaf(w, e1.z, eacc[6]); eacc[7] = fmaf(w, e1.w, eacc[7]);
        ws += w;
    }

    // store partials
    float* vp = g_vp + (size_t)jh * NROWS * DMID + (size_t)row * DMID + hd;
    float4* vp4 = (float4*)vp;
    vp4[0] = make_float4(vacc[0], vacc[1], vacc[2], vacc[3]);
    vp4[1] = make_float4(vacc[4], vacc[5], vacc[6], vacc[7]);
    vp4[2] = make_float4(vacc[8], vacc[9], vacc[10], vacc[11]);
    vp4[3] = make_float4(vacc[12], vacc[13], vacc[14], vacc[15]);
    float* epo = g_ep + (size_t)jh * NROWS * HH * DE + ((size_t)row * HH + h) * DE;
    float4* ep4 = (float4*)epo;
    ep4[0] = make_float4(eacc[0], eacc[1], eacc[2], eacc[3]);
    ep4[1] = make_float4(eacc[4], eacc[5], eacc[6], eacc[7]);
    g_ws[(size_t)jh * NROWS * HH + row * HH + h] = ws;
}

// ---------------- combine + gated residual + sigmoid gate + LN + ReLU ----------------
__global__ void __launch_bounds__(128) epilogue_kernel(
    const float* __restrict__ Wg, const float* __restrict__ lng,
    const float* __restrict__ lnb, const float* __restrict__ We,
    const float* __restrict__ be, float* __restrict__ xout, int to_gx)
{
    const int row = blockIdx.x;
    const int t = threadIdx.x;
    const int h = t >> 4;            // t/16

    // combine attention partials: o = (vacc + eacc@We + ws*be) / s
    float vtot = g_vp[(size_t)row * DMID + t]
               + g_vp[(size_t)NROWS * DMID + (size_t)row * DMID + t];
    float ws = g_ws[row * HH + h] + g_ws[NROWS * HH + row * HH + h];
    float o = fmaf(ws, be[t], vtot);
    const size_t eb = ((size_t)row * HH + h) * DE;
    #pragma unroll
    for (int c = 0; c < DE; c++) {
        float ec = g_ep[eb + c] + g_ep[(size_t)NROWS * HH * DE + eb + c];
        o = fmaf(ec, We[c * DMID + t], o);
    }
    const float s = (ws == 0.f) ? 1.f : ws;
    o /= s;

    const float r = g_res[(size_t)row * DMID + t];

    float p = o * Wg[t] + r * Wg[DMID + t] + (o - r) * Wg[2 * DMID + t];

    __shared__ float red[4], r1[4], r2[4];
    float sgate = p;
    #pragma unroll
    for (int off = 16; off; off >>= 1)
        sgate += __shfl_xor_sync(0xffffffffu, sgate, off);
    if ((t & 31) == 0) red[t >> 5] = sgate;
    __syncthreads();
    const float tot = red[0] + red[1] + red[2] + red[3];
    const float g = 1.f / (1.f + __expf(-tot));
    const float y = o * g + r * (1.f - g);

    float s1 = y, s2 = y * y;
    #pragma unroll
    for (int off = 16; off; off >>= 1) {
        s1 += __shfl_xor_sync(0xffffffffu, s1, off);
        s2 += __shfl_xor_sync(0xffffffffu, s2, off);
    }
    if ((t & 31) == 0) { r1[t >> 5] = s1; r2[t >> 5] = s2; }
    __syncthreads();
    const float mu = (r1[0] + r1[1] + r1[2] + r1[3]) * (1.f / DMID);
    const float m2 = (r2[0] + r2[1] + r2[2] + r2[3]) * (1.f / DMID);
    const float var = m2 - mu * mu;
    const float yn = (y - mu) * rsqrtf(var + 1e-5f) * lng[t] + lnb[t];
    const float res = fmaxf(yn, 0.f);

    if (to_gx) g_x[(size_t)row * DMID + t] = res;
    else       xout[(size_t)row * DMID + t] = res;
}

// ---------------- launcher ----------------
extern "C" void kernel_launch(void* const* d_in, const int* in_sizes, int n_in,
                              void* d_out, int out_size)
{
    const float* nodes = (const float*)d_in[0];
    const float* edges = (const float*)d_in[1];
    const float* adj   = (const float*)d_in[2];
    const float* Wq = (const float*)d_in[3];
    const float* bq = (const float*)d_in[4];
    const float* Wk = (const float*)d_in[5];
    const float* bk = (const float*)d_in[6];
    const float* Wv = (const float*)d_in[7];
    const float* bv = (const float*)d_in[8];
    const float* We = (const float*)d_in[9];
    const float* be = (const float*)d_in[10];
    const float* Wr = (const float*)d_in[11];
    const float* br = (const float*)d_in[12];
    const float* Wg = (const float*)d_in[13];
    const float* lng = (const float*)d_in[14];
    const float* lnb = (const float*)d_in[15];
    float* out = (float*)d_out;

    for (int l = 0; l < LL; l++) {
        const int wofs = l * DMID * DMID;   // 16384
        const int bofs = l * DMID;          // 128
        const int eofs = l * DE * DMID;     // 1024
        const int gofs = l * 3 * DMID;      // 384

        proj_kernel<<<dim3(NROWS / 16, 4), 128>>>(
            nodes, (l == 0) ? 0 : 1,
            Wq + wofs, bq + bofs, Wk + wofs, bk + bofs,
            Wv + wofs, bv + bofs, Wr + wofs, br + bofs);

        means_kernel<<<NN, 256>>>(edges, We + eofs, be + bofs);

        attn2_kernel<<<dim3(NN / TI, JS, BB), 128>>>(edges, adj, We + eofs, be + bofs);

        epilogue_kernel<<<NROWS, 128>>>(
            Wg + gofs, lng + bofs, lnb + bofs, We + eofs, be + bofs,
            out, (l == LL - 1) ? 0 : 1);
    }
}